// round 9
// baseline (speedup 1.0000x reference)
#include <cuda_runtime.h>
#include <cuda_bf16.h>
#include <math_constants.h>
#include <cstdint>

// Problem constants (fixed dataset shapes)
#define NMAX 20000
#define EMAX 320000
#define ETOT (EMAX + NMAX)

// ---------------- device scratch (static allocations only) ----------------
__device__ float g_h1[(size_t)NMAX * 128];
__device__ float g_h2[(size_t)NMAX * 128];
__device__ float g_xlxr[(size_t)NMAX * 1024];    // layer1 & actor: [xl(512) | xr(512)]
__device__ float g_xlxr2[(size_t)NMAX * 1024];   // critic
__device__ float g_al[(size_t)NMAX * 4];         // 0.6 * att . xl  per node/head
__device__ int   g_cnt[NMAX];
__device__ int   g_rp[NMAX + 1];
__device__ int   g_cur[NMAX];
__device__ int   g_csrc[ETOT];

// bf16 hi/lo activations
__device__ __nv_bfloat16 g_ahi[(size_t)NMAX * 128];
__device__ __nv_bfloat16 g_alo[(size_t)NMAX * 128];
// transposed bf16 hi/lo weights: rows = 128(W_in) + 6*512 = 3200, each row 128 bf16
#define WT_ROWS 3200
__device__ __nv_bfloat16 g_wthi[(size_t)WT_ROWS * 128];
__device__ __nv_bfloat16 g_wtlo[(size_t)WT_ROWS * 128];
// packed biases, index-matched to wt rows
__device__ float g_biasc[WT_ROWS];

// ---------------- CSR build ----------------
__global__ void count_k(const int* __restrict__ dstv, int E) {
    int i = blockIdx.x * blockDim.x + threadIdx.x;
    if (i < E) atomicAdd(&g_cnt[dstv[i]], 1);
}
__global__ void scan2_k(int N) {
    __shared__ int wsum[32];
    int tid = threadIdx.x;
    int lane = tid & 31, wid = tid >> 5;
    int per = (N + 1023) >> 10;
    int start = tid * per;
    int s = 0;
    for (int i = 0; i < per; ++i) {
        int idx = start + i;
        if (idx < N) s += g_cnt[idx];
    }
    int v = s;
    #pragma unroll
    for (int off = 1; off < 32; off <<= 1) {
        int t = __shfl_up_sync(0xffffffffu, v, off);
        if (lane >= off) v += t;
    }
    if (lane == 31) wsum[wid] = v;
    __syncthreads();
    if (wid == 0) {
        int w = wsum[lane];
        #pragma unroll
        for (int off = 1; off < 32; off <<= 1) {
            int t = __shfl_up_sync(0xffffffffu, w, off);
            if (lane >= off) w += t;
        }
        wsum[lane] = w;
    }
    __syncthreads();
    int excl = v - s + (wid ? wsum[wid - 1] : 0);
    int run = excl;
    for (int i = 0; i < per; ++i) {
        int idx = start + i;
        if (idx < N) {
            int c = g_cnt[idx];
            g_cur[idx] = run;
            run += c;
            g_rp[idx + 1] = run;
        }
    }
    if (tid == 0) g_rp[0] = 0;
}
__global__ void scatter_k(const int* __restrict__ srcv, const int* __restrict__ dstv,
                          int E, int N) {
    int i = blockIdx.x * blockDim.x + threadIdx.x;
    if (i < E) {
        int d = dstv[i];
        int pos = atomicAdd(&g_cur[d], 1);
        g_csrc[pos] = srcv[i];
    } else if (i < E + N) {
        int n = i - E;
        int pos = atomicAdd(&g_cur[n], 1);
        g_csrc[pos] = n;
    }
}

// ---------------- weights transpose + hi/lo + bias pack + cnt init, ONE launch ----------------
__device__ __forceinline__ uint32_t pack_bf2(__nv_bfloat16 a, __nv_bfloat16 b) {
    return (uint32_t)__bfloat16_as_ushort(a) | ((uint32_t)__bfloat16_as_ushort(b) << 16);
}

__global__ void conv_all_k(const float* __restrict__ w0, const float* __restrict__ w1,
                           const float* __restrict__ w2, const float* __restrict__ w3,
                           const float* __restrict__ w4, const float* __restrict__ w5,
                           const float* __restrict__ w6,
                           const float* __restrict__ b0, const float* __restrict__ b1,
                           const float* __restrict__ b2, const float* __restrict__ b3,
                           const float* __restrict__ b4, const float* __restrict__ b5,
                           const float* __restrict__ b6, int N) {
    int i = blockIdx.x * blockDim.x + threadIdx.x;
    if (i < N) g_cnt[i] = 1;   // self-loop pre-count
    // thread = (segment, output row n, k-group of 8)
    const int WTH = 2048 + 6 * 8192;   // 51200
    if (i < WTH) {
        const float* W; int cols, rowoff, n, kg;
        if (i < 2048) { W = w0; cols = 128; rowoff = 0; n = i & 127; kg = i >> 7; }
        else {
            int j = i - 2048;
            int s = j >> 13;
            int r = j & 8191;
            n = r & 511; kg = r >> 9;
            W = (s == 0) ? w1 : (s == 1) ? w2 : (s == 2) ? w3 : (s == 3) ? w4 : (s == 4) ? w5 : w6;
            cols = 512; rowoff = 128 + s * 512;
        }
        int k0 = kg * 8;
        __nv_bfloat16 h8[8], l8v[8];
        #pragma unroll
        for (int q = 0; q < 8; ++q) {
            float v = W[(size_t)(k0 + q) * cols + n];
            __nv_bfloat16 h = __float2bfloat16(v);
            h8[q] = h;
            l8v[q] = __float2bfloat16(v - __bfloat162float(h));
        }
        uint4 hv, lv;
        hv.x = pack_bf2(h8[0], h8[1]); hv.y = pack_bf2(h8[2], h8[3]);
        hv.z = pack_bf2(h8[4], h8[5]); hv.w = pack_bf2(h8[6], h8[7]);
        lv.x = pack_bf2(l8v[0], l8v[1]); lv.y = pack_bf2(l8v[2], l8v[3]);
        lv.z = pack_bf2(l8v[4], l8v[5]); lv.w = pack_bf2(l8v[6], l8v[7]);
        *(uint4*)(g_wthi + (size_t)(rowoff + n) * 128 + k0) = hv;
        *(uint4*)(g_wtlo + (size_t)(rowoff + n) * 128 + k0) = lv;
    } else if (i < WTH + WT_ROWS) {
        int j = i - WTH;
        float v;
        if (j < 128) v = b0[j];
        else {
            int s = (j - 128) >> 9, t = (j - 128) & 511;
            const float* B = (s == 0) ? b1 : (s == 1) ? b2 : (s == 2) ? b3
                           : (s == 3) ? b4 : (s == 4) ? b5 : b6;
            v = B[t];
        }
        g_biasc[j] = v;
    }
}

// ---------------- activation fp32 -> bf16 hi/lo (x only) ----------------
__global__ void conv_a_k(const float* __restrict__ src, int n4) {
    int i = blockIdx.x * blockDim.x + threadIdx.x;
    if (i < n4) {
        float4 v = ((const float4*)src)[i];
        __nv_bfloat16 hx = __float2bfloat16(v.x);
        __nv_bfloat16 hy = __float2bfloat16(v.y);
        __nv_bfloat16 hz = __float2bfloat16(v.z);
        __nv_bfloat16 hw = __float2bfloat16(v.w);
        __nv_bfloat16 lx = __float2bfloat16(v.x - __bfloat162float(hx));
        __nv_bfloat16 ly = __float2bfloat16(v.y - __bfloat162float(hy));
        __nv_bfloat16 lz = __float2bfloat16(v.z - __bfloat162float(hz));
        __nv_bfloat16 lw = __float2bfloat16(v.w - __bfloat162float(hw));
        ((uint2*)g_ahi)[i] = make_uint2(pack_bf2(hx, hy), pack_bf2(hz, hw));
        ((uint2*)g_alo)[i] = make_uint2(pack_bf2(lx, ly), pack_bf2(lz, lw));
    }
}

// ---------------- per-node al = 0.6 * att . xl ----------------
__global__ void __launch_bounds__(256)
al_k(const float* __restrict__ xlxr, const float* __restrict__ att, int N) {
    int n    = (blockIdx.x * blockDim.x + threadIdx.x) >> 5;
    int lane = threadIdx.x & 31;
    if (n >= N) return;
    int g = lane >> 3, l8 = lane & 7;
    int cb = g * 32 + l8 * 4;
    const float4* ap = (const float4*)att + cb;
    const float4* xp = (const float4*)(xlxr + (size_t)n * 1024) + cb;
    float s = 0.f;
    #pragma unroll
    for (int j = 0; j < 4; ++j) {
        float4 a = ap[j], x = xp[j];
        s = fmaf(x.x, a.x, fmaf(x.y, a.y, fmaf(x.z, a.z, fmaf(x.w, a.w, s))));
    }
    s += __shfl_xor_sync(0xffffffffu, s, 1);
    s += __shfl_xor_sync(0xffffffffu, s, 2);
    s += __shfl_xor_sync(0xffffffffu, s, 4);
    if (l8 == 0) g_al[(size_t)n * 4 + g] = 0.6f * s;
}

// ======== bf16x3 GEMM v4: persistent col tile, double-buffered A, 512 threads ========
#define TSTRIDE 272
#define TILE_B (128 * TSTRIDE)
#define GMM_SMEM (6 * TILE_B)

__device__ __forceinline__ uint32_t smem_u32(const void* p) {
    uint32_t a;
    asm("{ .reg .u64 t; cvta.to.shared.u64 t, %1; cvt.u32.u64 %0, t; }" : "=r"(a) : "l"(p));
    return a;
}

#define CP16(dst, src, sz) \
    asm volatile("cp.async.cg.shared.global [%0], [%1], 16, %2;" \
                 :: "r"(dst), "l"(src), "r"(sz) : "memory")
#define CP_COMMIT() asm volatile("cp.async.commit_group;" ::: "memory")
#define CP_WAIT0()  asm volatile("cp.async.wait_group 0;" ::: "memory")
#define CP_WAIT1()  asm volatile("cp.async.wait_group 1;" ::: "memory")

#define LDMX4(r0, r1, r2, r3, addr) \
    asm volatile("ldmatrix.sync.aligned.m8n8.x4.shared.b16 {%0,%1,%2,%3}, [%4];" \
                 : "=r"(r0), "=r"(r1), "=r"(r2), "=r"(r3) : "r"(addr))

#define MMA_BF16(c, a0, a1, a2, a3, b0, b1) \
    asm volatile("mma.sync.aligned.m16n8k16.row.col.f32.bf16.bf16.f32 " \
                 "{%0,%1,%2,%3}, {%4,%5,%6,%7}, {%8,%9}, {%0,%1,%2,%3};" \
                 : "+f"((c)[0]), "+f"((c)[1]), "+f"((c)[2]), "+f"((c)[3]) \
                 : "r"(a0), "r"(a1), "r"(a2), "r"(a3), "r"(b0), "r"(b1))

__device__ __forceinline__ void prefetch_A(uint32_t uAhi, uint32_t uAlo,
                                           const __nv_bfloat16* Ahi, const __nv_bfloat16* Alo,
                                           int row0, int M, int tid) {
    #pragma unroll
    for (int it = 0; it < 4; ++it) {
        int idx = it * 512 + tid;
        int row = idx >> 4, c = idx & 15;
        int grow = row0 + row;
        int ok = grow < M;
        int srow = ok ? grow : 0;
        uint32_t sz = ok ? 16u : 0u;
        CP16(uAhi + row * TSTRIDE + c * 16,
             (const char*)(Ahi + (size_t)srow * 128) + c * 16, sz);
        CP16(uAlo + row * TSTRIDE + c * 16,
             (const char*)(Alo + (size_t)srow * 128) + c * 16, sz);
    }
}

__global__ void __launch_bounds__(512, 1)
gemm_mma_k(const __nv_bfloat16* __restrict__ Ahi, const __nv_bfloat16* __restrict__ Alo, int M,
           const __nv_bfloat16* __restrict__ Bhi, const __nv_bfloat16* __restrict__ Blo,
           const float* __restrict__ bias,
           float* __restrict__ out, float* __restrict__ out2, int split,
           int ldo, int do_relu, int conv_out) {
    extern __shared__ char sm[];
    char* sBhi = sm;
    char* sBlo = sm + TILE_B;
    char* sA[2][2];
    sA[0][0] = sm + 2 * TILE_B;
    sA[0][1] = sm + 3 * TILE_B;
    sA[1][0] = sm + 4 * TILE_B;
    sA[1][1] = sm + 5 * TILE_B;

    int tid = threadIdx.x;
    int wc0 = blockIdx.y * 128;
    int oc  = wc0;
    if (oc >= split) { out = out2; oc -= split; }

    uint32_t uBhi = smem_u32(sBhi), uBlo = smem_u32(sBlo);
    uint32_t uA[2][2];
    #pragma unroll
    for (int s = 0; s < 2; ++s) { uA[s][0] = smem_u32(sA[s][0]); uA[s][1] = smem_u32(sA[s][1]); }

    #pragma unroll
    for (int it = 0; it < 4; ++it) {
        int idx = it * 512 + tid;
        int row = idx >> 4, c = idx & 15;
        CP16(uBhi + row * TSTRIDE + c * 16,
             (const char*)(Bhi + (size_t)(wc0 + row) * 128) + c * 16, 16u);
        CP16(uBlo + row * TSTRIDE + c * 16,
             (const char*)(Blo + (size_t)(wc0 + row) * 128) + c * 16, 16u);
    }
    int nrt = (M + 127) >> 7;
    int stride = gridDim.x;
    int r0 = blockIdx.x;
    if (r0 < nrt)
        prefetch_A(uA[0][0], uA[0][1], Ahi, Alo, r0 * 128, M, tid);
    CP_COMMIT();

    int wid = tid >> 5;
    int lane = tid & 31;
    int m0 = (wid & 3) * 32;
    int n0 = (wid >> 2) * 32;

    int gq = lane >> 3, l8 = lane & 7;
    int fr_row = (gq & 1) * 8 + l8;
    int fr_col = (gq >> 1) * 16;

    uint32_t aoff[2], boff[2];
    #pragma unroll
    for (int mt = 0; mt < 2; ++mt)
        aoff[mt] = (uint32_t)((m0 + mt * 16 + fr_row) * TSTRIDE + fr_col);
    #pragma unroll
    for (int nt2 = 0; nt2 < 2; ++nt2)
        boff[nt2] = (uint32_t)((n0 + nt2 * 16 + fr_row) * TSTRIDE + fr_col);

    int qr = lane >> 2;
    int qc = (lane & 3) * 2;
    float2 bv[4];
    #pragma unroll
    for (int nt = 0; nt < 4; ++nt)
        bv[nt] = *(const float2*)(bias + wc0 + n0 + nt * 8 + qc);

    int buf = 0;
    for (int r = r0; r < nrt; r += stride) {
        int rn = r + stride;
        if (rn < nrt)
            prefetch_A(uA[buf ^ 1][0], uA[buf ^ 1][1], Ahi, Alo, rn * 128, M, tid);
        CP_COMMIT();
        if (rn < nrt) CP_WAIT1(); else CP_WAIT0();
        __syncthreads();

        uint32_t uAhi = uA[buf][0], uAlo = uA[buf][1];

        float c[2][4][4];
        #pragma unroll
        for (int mt = 0; mt < 2; ++mt)
            #pragma unroll
            for (int nt = 0; nt < 4; ++nt)
                #pragma unroll
                for (int q = 0; q < 4; ++q) c[mt][nt][q] = 0.f;

        #pragma unroll
        for (int kk = 0; kk < 8; ++kk) {
            uint32_t ah[2][4], al2[2][4];
            #pragma unroll
            for (int mt = 0; mt < 2; ++mt) {
                LDMX4(ah[mt][0], ah[mt][1], ah[mt][2], ah[mt][3], uAhi + aoff[mt] + kk * 32);
                LDMX4(al2[mt][0], al2[mt][1], al2[mt][2], al2[mt][3], uAlo + aoff[mt] + kk * 32);
            }
            uint32_t bh[2][4], bl[2][4];
            #pragma unroll
            for (int nt2 = 0; nt2 < 2; ++nt2) {
                LDMX4(bh[nt2][0], bh[nt2][1], bh[nt2][2], bh[nt2][3], uBhi + boff[nt2] + kk * 32);
                LDMX4(bl[nt2][0], bl[nt2][1], bl[nt2][2], bl[nt2][3], uBlo + boff[nt2] + kk * 32);
            }
            #pragma unroll
            for (int mt = 0; mt < 2; ++mt)
                #pragma unroll
                for (int nt = 0; nt < 4; ++nt) {
                    int nt2 = nt >> 1, odd = nt & 1;
                    MMA_BF16(c[mt][nt], ah[mt][0], ah[mt][1], ah[mt][2], ah[mt][3],
                             bh[nt2][odd], bh[nt2][2 + odd]);
                    MMA_BF16(c[mt][nt], ah[mt][0], ah[mt][1], ah[mt][2], ah[mt][3],
                             bl[nt2][odd], bl[nt2][2 + odd]);
                    MMA_BF16(c[mt][nt], al2[mt][0], al2[mt][1], al2[mt][2], al2[mt][3],
                             bh[nt2][odd], bh[nt2][2 + odd]);
                }
        }

        int row0 = r * 128;
        #pragma unroll
        for (int mt = 0; mt < 2; ++mt) {
            int r_lo = row0 + m0 + mt * 16 + qr;
            #pragma unroll
            for (int nt = 0; nt < 4; ++nt) {
                int colb = n0 + nt * 8 + qc;
                float2 v0 = make_float2(c[mt][nt][0] + bv[nt].x, c[mt][nt][1] + bv[nt].y);
                float2 v1 = make_float2(c[mt][nt][2] + bv[nt].x, c[mt][nt][3] + bv[nt].y);
                if (do_relu) {
                    v0.x = fmaxf(v0.x, 0.f); v0.y = fmaxf(v0.y, 0.f);
                    v1.x = fmaxf(v1.x, 0.f); v1.y = fmaxf(v1.y, 0.f);
                }
                #pragma unroll
                for (int half = 0; half < 2; ++half) {
                    int rr = r_lo + half * 8;
                    float2 vv = half ? v1 : v0;
                    if (rr < M) {
                        *(float2*)(out + (size_t)rr * ldo + oc + colb) = vv;
                        if (conv_out) {
                            __nv_bfloat16 hx = __float2bfloat16(vv.x);
                            __nv_bfloat16 hy = __float2bfloat16(vv.y);
                            __nv_bfloat16 lx = __float2bfloat16(vv.x - __bfloat162float(hx));
                            __nv_bfloat16 ly = __float2bfloat16(vv.y - __bfloat162float(hy));
                            size_t ai = (size_t)rr * 128 + oc + colb;
                            *(uint32_t*)(g_ahi + ai) = pack_bf2(hx, hy);
                            *(uint32_t*)(g_alo + ai) = pack_bf2(lx, ly);
                        }
                    }
                }
            }
        }
        __syncthreads();
        buf ^= 1;
    }
}

// ============ GATv2 v3: abs-identity score + precomputed al + rescale-skip ============
// score = al[src] + ar[dst] + sum_c (0.4*att_c) * |xl_c + xr_c|
#define LRDA(t, x4, r4, a4) do {                                          \
    float ex = (x4).x + (r4).x; t = fmaf(fabsf(ex), (a4).x, t);           \
    float ey = (x4).y + (r4).y; t = fmaf(fabsf(ey), (a4).y, t);           \
    float ez = (x4).z + (r4).z; t = fmaf(fabsf(ez), (a4).z, t);           \
    float ew = (x4).w + (r4).w; t = fmaf(fabsf(ew), (a4).w, t);           \
} while (0)

template <int WRITE_H>
__global__ void __launch_bounds__(256)
gat2_k(const float* __restrict__ xlxr,
       const float* __restrict__ hres,
       const float* __restrict__ att,
       const float* __restrict__ gatb,
       const float* __restrict__ lng,
       const float* __restrict__ lnb,
       const float* __restrict__ headW,
       const float* __restrict__ headb,
       float* __restrict__ outh,
       float* __restrict__ outsc,
       int N) {
    int n    = (blockIdx.x * blockDim.x + threadIdx.x) >> 5;
    int lane = threadIdx.x & 31;
    if (n >= N) return;
    int g  = lane >> 3;
    int l8 = lane & 7;
    int cb = g * 32 + l8 * 4;

    float4 atv[4], xrv[4];
    const float4* ap = (const float4*)att + cb;
    const float4* xp = (const float4*)(xlxr + (size_t)n * 1024 + 512) + cb;
    #pragma unroll
    for (int j = 0; j < 4; ++j) { atv[j] = ap[j]; xrv[j] = xp[j]; }

    // ar = 0.6 * att . xr  (this node's destination term), then scale att by 0.4
    float ar_n = 0.f;
    #pragma unroll
    for (int j = 0; j < 4; ++j) {
        ar_n = fmaf(xrv[j].x, atv[j].x, ar_n);
        ar_n = fmaf(xrv[j].y, atv[j].y, ar_n);
        ar_n = fmaf(xrv[j].z, atv[j].z, ar_n);
        ar_n = fmaf(xrv[j].w, atv[j].w, ar_n);
    }
    ar_n += __shfl_xor_sync(0xffffffffu, ar_n, 1);
    ar_n += __shfl_xor_sync(0xffffffffu, ar_n, 2);
    ar_n += __shfl_xor_sync(0xffffffffu, ar_n, 4);
    ar_n *= 0.6f;
    #pragma unroll
    for (int j = 0; j < 4; ++j) {
        atv[j].x *= 0.4f; atv[j].y *= 0.4f; atv[j].z *= 0.4f; atv[j].w *= 0.4f;
    }

    float m = -CUDART_INF_F, d = 0.f;
    float4 acc[4];
    #pragma unroll
    for (int j = 0; j < 4; ++j) acc[j] = make_float4(0.f, 0.f, 0.f, 0.f);

    int e = g_rp[n], end = g_rp[n + 1];
    for (; e + 2 <= end; e += 2) {
        int s0 = g_csrc[e];
        int s1 = g_csrc[e + 1];
        float a0 = g_al[(size_t)s0 * 4 + g];
        float a1 = g_al[(size_t)s1 * 4 + g];
        const float4* q0 = (const float4*)(xlxr + (size_t)s0 * 1024) + cb;
        const float4* q1 = (const float4*)(xlxr + (size_t)s1 * 1024) + cb;
        float4 x0[4], x1[4];
        #pragma unroll
        for (int j = 0; j < 4; ++j) x0[j] = q0[j];
        #pragma unroll
        for (int j = 0; j < 4; ++j) x1[j] = q1[j];

        float t0 = 0.f, t1 = 0.f;
        #pragma unroll
        for (int j = 0; j < 4; ++j) { LRDA(t0, x0[j], xrv[j], atv[j]); LRDA(t1, x1[j], xrv[j], atv[j]); }
        t0 += __shfl_xor_sync(0xffffffffu, t0, 1);
        t1 += __shfl_xor_sync(0xffffffffu, t1, 1);
        t0 += __shfl_xor_sync(0xffffffffu, t0, 2);
        t1 += __shfl_xor_sync(0xffffffffu, t1, 2);
        t0 += __shfl_xor_sync(0xffffffffu, t0, 4);
        t1 += __shfl_xor_sync(0xffffffffu, t1, 4);
        t0 += a0 + ar_n;
        t1 += a1 + ar_n;

        float mn = fmaxf(m, fmaxf(t0, t1));
        if (__any_sync(0xffffffffu, mn != m)) {
            float sc = __expf(m - mn);
            float p0 = __expf(t0 - mn);
            float p1 = __expf(t1 - mn);
            d = fmaf(d, sc, p0 + p1);
            #pragma unroll
            for (int j = 0; j < 4; ++j) {
                acc[j].x = fmaf(acc[j].x, sc, fmaf(p0, x0[j].x, p1 * x1[j].x));
                acc[j].y = fmaf(acc[j].y, sc, fmaf(p0, x0[j].y, p1 * x1[j].y));
                acc[j].z = fmaf(acc[j].z, sc, fmaf(p0, x0[j].z, p1 * x1[j].z));
                acc[j].w = fmaf(acc[j].w, sc, fmaf(p0, x0[j].w, p1 * x1[j].w));
            }
            m = mn;
        } else {
            float p0 = __expf(t0 - m);
            float p1 = __expf(t1 - m);
            d += p0 + p1;
            #pragma unroll
            for (int j = 0; j < 4; ++j) {
                acc[j].x = fmaf(p1, x1[j].x, fmaf(p0, x0[j].x, acc[j].x));
                acc[j].y = fmaf(p1, x1[j].y, fmaf(p0, x0[j].y, acc[j].y));
                acc[j].z = fmaf(p1, x1[j].z, fmaf(p0, x0[j].z, acc[j].z));
                acc[j].w = fmaf(p1, x1[j].w, fmaf(p0, x0[j].w, acc[j].w));
            }
        }
    }
    if (e < end) {
        int s0 = g_csrc[e];
        float a0 = g_al[(size_t)s0 * 4 + g];
        const float4* q0 = (const float4*)(xlxr + (size_t)s0 * 1024) + cb;
        float4 x0[4];
        #pragma unroll
        for (int j = 0; j < 4; ++j) x0[j] = q0[j];
        float t0 = 0.f;
        #pragma unroll
        for (int j = 0; j < 4; ++j) LRDA(t0, x0[j], xrv[j], atv[j]);
        t0 += __shfl_xor_sync(0xffffffffu, t0, 1);
        t0 += __shfl_xor_sync(0xffffffffu, t0, 2);
        t0 += __shfl_xor_sync(0xffffffffu, t0, 4);
        t0 += a0 + ar_n;
        float mn = fmaxf(m, t0);
        if (__any_sync(0xffffffffu, mn != m)) {
            float sc = __expf(m - mn);
            float p0 = __expf(t0 - mn);
            d = fmaf(d, sc, p0);
            #pragma unroll
            for (int j = 0; j < 4; ++j) {
                acc[j].x = fmaf(acc[j].x, sc, p0 * x0[j].x);
                acc[j].y = fmaf(acc[j].y, sc, p0 * x0[j].y);
                acc[j].z = fmaf(acc[j].z, sc, p0 * x0[j].z);
                acc[j].w = fmaf(acc[j].w, sc, p0 * x0[j].w);
            }
            m = mn;
        } else {
            float p0 = __expf(t0 - m);
            d += p0;
            #pragma unroll
            for (int j = 0; j < 4; ++j) {
                acc[j].x = fmaf(p0, x0[j].x, acc[j].x);
                acc[j].y = fmaf(p0, x0[j].y, acc[j].y);
                acc[j].z = fmaf(p0, x0[j].z, acc[j].z);
                acc[j].w = fmaf(p0, x0[j].w, acc[j].w);
            }
        }
    }

    float inv = 0.25f / d;
    float* a = (float*)acc;
    #pragma unroll
    for (int i = 0; i < 16; ++i) {
        float v = a[i] * inv;
        v += __shfl_xor_sync(0xffffffffu, v, 8);
        v += __shfl_xor_sync(0xffffffffu, v, 16);
        a[i] = v;
    }

    int fb = l8 * 4;
    const float4* gbp = (const float4*)gatb + fb;
    const float4* hrp = (const float4*)(hres + (size_t)n * 128) + fb;
    float4 v4[4];
    float s1 = 0.f, s2 = 0.f;
    #pragma unroll
    for (int j = 0; j < 4; ++j) {
        float4 gb = gbp[j], hr = hrp[j];
        v4[j].x = acc[j].x + gb.x + hr.x;
        v4[j].y = acc[j].y + gb.y + hr.y;
        v4[j].z = acc[j].z + gb.z + hr.z;
        v4[j].w = acc[j].w + gb.w + hr.w;
        s1 += v4[j].x + v4[j].y + v4[j].z + v4[j].w;
        s2 += v4[j].x * v4[j].x + v4[j].y * v4[j].y + v4[j].z * v4[j].z + v4[j].w * v4[j].w;
    }
    s1 += __shfl_xor_sync(0xffffffffu, s1, 1);
    s2 += __shfl_xor_sync(0xffffffffu, s2, 1);
    s1 += __shfl_xor_sync(0xffffffffu, s1, 2);
    s2 += __shfl_xor_sync(0xffffffffu, s2, 2);
    s1 += __shfl_xor_sync(0xffffffffu, s1, 4);
    s2 += __shfl_xor_sync(0xffffffffu, s2, 4);
    float mean = s1 * (1.f / 128.f);
    float var  = s2 * (1.f / 128.f) - mean * mean;
    float rstd = rsqrtf(var + 1e-5f);

    const float4* gp = (const float4*)lng + fb;
    const float4* bp = (const float4*)lnb + fb;
    float4 y4[4];
    #pragma unroll
    for (int j = 0; j < 4; ++j) {
        float4 gg = gp[j], bb = bp[j];
        y4[j].x = fmaxf((v4[j].x - mean) * rstd * gg.x + bb.x, 0.f);
        y4[j].y = fmaxf((v4[j].y - mean) * rstd * gg.y + bb.y, 0.f);
        y4[j].z = fmaxf((v4[j].z - mean) * rstd * gg.z + bb.z, 0.f);
        y4[j].w = fmaxf((v4[j].w - mean) * rstd * gg.w + bb.w, 0.f);
    }

    if (WRITE_H) {
        if (g == 0) {
            float4* op = (float4*)outh + (size_t)n * 32 + fb;
            #pragma unroll
            for (int j = 0; j < 4; ++j) {
                op[j] = y4[j];
                __nv_bfloat16 hx = __float2bfloat16(y4[j].x);
                __nv_bfloat16 hy = __float2bfloat16(y4[j].y);
                __nv_bfloat16 hz = __float2bfloat16(y4[j].z);
                __nv_bfloat16 hw = __float2bfloat16(y4[j].w);
                __nv_bfloat16 lx = __float2bfloat16(y4[j].x - __bfloat162float(hx));
                __nv_bfloat16 ly = __float2bfloat16(y4[j].y - __bfloat162float(hy));
                __nv_bfloat16 lz = __float2bfloat16(y4[j].z - __bfloat162float(hz));
                __nv_bfloat16 lw = __float2bfloat16(y4[j].w - __bfloat162float(hw));
                size_t ai = (size_t)n * 32 + fb + j;
                ((uint2*)g_ahi)[ai] = make_uint2(pack_bf2(hx, hy), pack_bf2(hz, hw));
                ((uint2*)g_alo)[ai] = make_uint2(pack_bf2(lx, ly), pack_bf2(lz, lw));
            }
        }
    } else {
        const float4* wp = (const float4*)headW + fb;
        float pp = 0.f;
        #pragma unroll
        for (int j = 0; j < 4; ++j) {
            float4 w4 = wp[j];
            pp = fmaf(y4[j].x, w4.x, pp);
            pp = fmaf(y4[j].y, w4.y, pp);
            pp = fmaf(y4[j].z, w4.z, pp);
            pp = fmaf(y4[j].w, w4.w, pp);
        }
        pp += __shfl_xor_sync(0xffffffffu, pp, 1);
        pp += __shfl_xor_sync(0xffffffffu, pp, 2);
        pp += __shfl_xor_sync(0xffffffffu, pp, 4);
        if (lane == 0) outsc[n] = pp + headb[0];
    }
}

// ---------------- launch ----------------
extern "C" void kernel_launch(void* const* d_in, const int* in_sizes, int n_in,
                              void* d_out, int out_size) {
    const float* x     = (const float*)d_in[0];
    const int*   ei    = (const int*)d_in[1];
    const float* W_in  = (const float*)d_in[2];
    const float* b_in  = (const float*)d_in[3];
    const float* c1_Wl = (const float*)d_in[4];
    const float* c1_bl = (const float*)d_in[5];
    const float* c1_Wr = (const float*)d_in[6];
    const float* c1_br = (const float*)d_in[7];
    const float* c1_att= (const float*)d_in[8];
    const float* c1_b  = (const float*)d_in[9];
    const float* ln1_g = (const float*)d_in[10];
    const float* ln1_b = (const float*)d_in[11];
    const float* a_Wl  = (const float*)d_in[12];
    const float* a_bl  = (const float*)d_in[13];
    const float* a_Wr  = (const float*)d_in[14];
    const float* a_br  = (const float*)d_in[15];
    const float* a_att = (const float*)d_in[16];
    const float* a_b   = (const float*)d_in[17];
    const float* aln_g = (const float*)d_in[18];
    const float* aln_b = (const float*)d_in[19];
    const float* ah_W  = (const float*)d_in[20];
    const float* ah_b  = (const float*)d_in[21];
    const float* k_Wl  = (const float*)d_in[22];
    const float* k_bl  = (const float*)d_in[23];
    const float* k_Wr  = (const float*)d_in[24];
    const float* k_br  = (const float*)d_in[25];
    const float* k_att = (const float*)d_in[26];
    const float* k_b   = (const float*)d_in[27];
    const float* kln_g = (const float*)d_in[28];
    const float* kln_b = (const float*)d_in[29];
    const float* kh_W  = (const float*)d_in[30];
    const float* kh_b  = (const float*)d_in[31];

    int N = in_sizes[0] / 128;
    int E = in_sizes[1] / 2;
    float* out = (float*)d_out;

    float *h1, *h2, *xlxr, *xlxr2, *biasc;
    __nv_bfloat16 *ahi, *alo, *wthi, *wtlo;
    cudaGetSymbolAddress((void**)&h1, g_h1);
    cudaGetSymbolAddress((void**)&h2, g_h2);
    cudaGetSymbolAddress((void**)&xlxr, g_xlxr);
    cudaGetSymbolAddress((void**)&xlxr2, g_xlxr2);
    cudaGetSymbolAddress((void**)&biasc, g_biasc);
    cudaGetSymbolAddress((void**)&ahi, g_ahi);
    cudaGetSymbolAddress((void**)&alo, g_alo);
    cudaGetSymbolAddress((void**)&wthi, g_wthi);
    cudaGetSymbolAddress((void**)&wtlo, g_wtlo);

    cudaFuncSetAttribute(gemm_mma_k, cudaFuncAttributeMaxDynamicSharedMemorySize, GMM_SMEM);

    int gg = (N + 7) / 8;
    int gc = (N * 32 + 255) / 256;
    const int NOSPLIT = 1 << 30;

    conv_all_k<<<(2048 + 6 * 8192 + WT_ROWS + 255) / 256, 256>>>(          // 1
        W_in, c1_Wl, c1_Wr, a_Wl, a_Wr, k_Wl, k_Wr,
        b_in, c1_bl, c1_br, a_bl, a_br, k_bl, k_br, N);
    conv_a_k<<<gc, 256>>>(x, N * 32);                                      // 2
    gemm_mma_k<<<dim3(148, 1), 512, GMM_SMEM>>>(ahi, alo, N,               // 3: input layer
        wthi, wtlo, biasc, h1, (float*)0, NOSPLIT, 128, 1, 1);
    gemm_mma_k<<<dim3(18, 8), 512, GMM_SMEM>>>(ahi, alo, N,                // 4 <- profiled
        wthi + (size_t)128 * 128, wtlo + (size_t)128 * 128, biasc + 128,
        xlxr, (float*)0, NOSPLIT, 1024, 0, 0);

    count_k<<<(E + 255) / 256, 256>>>(ei + E, E);                          // 5
    scan2_k<<<1, 1024>>>(N);                                               // 6
    scatter_k<<<(E + N + 255) / 256, 256>>>(ei, ei + E, E, N);             // 7

    al_k<<<gg, 256>>>(xlxr, c1_att, N);                                    // 8
    gat2_k<1><<<gg, 256>>>(xlxr, h1, c1_att, c1_b, ln1_g, ln1_b,           // 9
                           (const float*)0, (const float*)0, h2, (float*)0, N);

    gemm_mma_k<<<dim3(9, 16), 512, GMM_SMEM>>>(ahi, alo, N,                // 10
        wthi + (size_t)1152 * 128, wtlo + (size_t)1152 * 128, biasc + 1152,
        xlxr, xlxr2, 1024, 1024, 0, 0);

    al_k<<<gg, 256>>>(xlxr, a_att, N);                                     // 11
    gat2_k<0><<<gg, 256>>>(xlxr, h2, a_att, a_b, aln_g, aln_b,             // 12
                           ah_W, ah_b, (float*)0, out, N);
    al_k<<<gg, 256>>>(xlxr2, k_att, N);                                    // 13
    gat2_k<0><<<gg, 256>>>(xlxr2, h2, k_att, k_b, kln_g, kln_b,            // 14
                           kh_W, kh_b, (float*)0, out + N, N);
}

// round 10
// speedup vs baseline: 1.1001x; 1.1001x over previous
#include <cuda_runtime.h>
#include <cuda_bf16.h>
#include <math_constants.h>
#include <cstdint>

// Problem constants (fixed dataset shapes)
#define NMAX 20000
#define EMAX 320000
#define ETOT (EMAX + NMAX)

// ---------------- device scratch (static allocations only) ----------------
__device__ float g_h1[(size_t)NMAX * 128];
__device__ float g_h2[(size_t)NMAX * 128];
__device__ float g_xlxr[(size_t)NMAX * 1024];    // layer1 & actor: [xl(512) | xr(512)]
__device__ float g_xlxr2[(size_t)NMAX * 1024];   // critic
__device__ int   g_cnt[NMAX];
__device__ int   g_rp[NMAX + 1];
__device__ int   g_cur[NMAX];
__device__ int   g_csrc[ETOT];

// bf16 hi/lo activations
__device__ __nv_bfloat16 g_ahi[(size_t)NMAX * 128];
__device__ __nv_bfloat16 g_alo[(size_t)NMAX * 128];
// transposed bf16 hi/lo weights: rows = 128(W_in) + 6*512 = 3200, each row 128 bf16
#define WT_ROWS 3200
__device__ __nv_bfloat16 g_wthi[(size_t)WT_ROWS * 128];
__device__ __nv_bfloat16 g_wtlo[(size_t)WT_ROWS * 128];
// packed biases, index-matched to wt rows
__device__ float g_biasc[WT_ROWS];

// ---------------- CSR build ----------------
__global__ void count_k(const int* __restrict__ dstv, int E) {
    int i = blockIdx.x * blockDim.x + threadIdx.x;
    if (i < E) atomicAdd(&g_cnt[dstv[i]], 1);
}
__global__ void scan2_k(int N) {
    __shared__ int wsum[32];
    int tid = threadIdx.x;
    int lane = tid & 31, wid = tid >> 5;
    int per = (N + 1023) >> 10;
    int start = tid * per;
    int s = 0;
    for (int i = 0; i < per; ++i) {
        int idx = start + i;
        if (idx < N) s += g_cnt[idx];
    }
    int v = s;
    #pragma unroll
    for (int off = 1; off < 32; off <<= 1) {
        int t = __shfl_up_sync(0xffffffffu, v, off);
        if (lane >= off) v += t;
    }
    if (lane == 31) wsum[wid] = v;
    __syncthreads();
    if (wid == 0) {
        int w = wsum[lane];
        #pragma unroll
        for (int off = 1; off < 32; off <<= 1) {
            int t = __shfl_up_sync(0xffffffffu, w, off);
            if (lane >= off) w += t;
        }
        wsum[lane] = w;
    }
    __syncthreads();
    int excl = v - s + (wid ? wsum[wid - 1] : 0);
    int run = excl;
    for (int i = 0; i < per; ++i) {
        int idx = start + i;
        if (idx < N) {
            int c = g_cnt[idx];
            g_cur[idx] = run;
            run += c;
            g_rp[idx + 1] = run;
        }
    }
    if (tid == 0) g_rp[0] = 0;
}
__global__ void scatter_k(const int* __restrict__ srcv, const int* __restrict__ dstv,
                          int E, int N) {
    int i = blockIdx.x * blockDim.x + threadIdx.x;
    if (i < E) {
        int d = dstv[i];
        int pos = atomicAdd(&g_cur[d], 1);
        g_csrc[pos] = srcv[i];
    } else if (i < E + N) {
        int n = i - E;
        int pos = atomicAdd(&g_cur[n], 1);
        g_csrc[pos] = n;
    }
}

// ---------------- weights transpose + hi/lo + bias pack + cnt init, ONE launch ----------------
__device__ __forceinline__ uint32_t pack_bf2(__nv_bfloat16 a, __nv_bfloat16 b) {
    return (uint32_t)__bfloat16_as_ushort(a) | ((uint32_t)__bfloat16_as_ushort(b) << 16);
}

__global__ void conv_all_k(const float* __restrict__ w0, const float* __restrict__ w1,
                           const float* __restrict__ w2, const float* __restrict__ w3,
                           const float* __restrict__ w4, const float* __restrict__ w5,
                           const float* __restrict__ w6,
                           const float* __restrict__ b0, const float* __restrict__ b1,
                           const float* __restrict__ b2, const float* __restrict__ b3,
                           const float* __restrict__ b4, const float* __restrict__ b5,
                           const float* __restrict__ b6, int N) {
    int i = blockIdx.x * blockDim.x + threadIdx.x;
    if (i < N) g_cnt[i] = 1;   // self-loop pre-count
    const int WTH = 2048 + 6 * 8192;   // 51200
    if (i < WTH) {
        const float* W; int cols, rowoff, n, kg;
        if (i < 2048) { W = w0; cols = 128; rowoff = 0; n = i & 127; kg = i >> 7; }
        else {
            int j = i - 2048;
            int s = j >> 13;
            int r = j & 8191;
            n = r & 511; kg = r >> 9;
            W = (s == 0) ? w1 : (s == 1) ? w2 : (s == 2) ? w3 : (s == 3) ? w4 : (s == 4) ? w5 : w6;
            cols = 512; rowoff = 128 + s * 512;
        }
        int k0 = kg * 8;
        __nv_bfloat16 h8[8], l8v[8];
        #pragma unroll
        for (int q = 0; q < 8; ++q) {
            float v = W[(size_t)(k0 + q) * cols + n];
            __nv_bfloat16 h = __float2bfloat16(v);
            h8[q] = h;
            l8v[q] = __float2bfloat16(v - __bfloat162float(h));
        }
        uint4 hv, lv;
        hv.x = pack_bf2(h8[0], h8[1]); hv.y = pack_bf2(h8[2], h8[3]);
        hv.z = pack_bf2(h8[4], h8[5]); hv.w = pack_bf2(h8[6], h8[7]);
        lv.x = pack_bf2(l8v[0], l8v[1]); lv.y = pack_bf2(l8v[2], l8v[3]);
        lv.z = pack_bf2(l8v[4], l8v[5]); lv.w = pack_bf2(l8v[6], l8v[7]);
        *(uint4*)(g_wthi + (size_t)(rowoff + n) * 128 + k0) = hv;
        *(uint4*)(g_wtlo + (size_t)(rowoff + n) * 128 + k0) = lv;
    } else if (i < WTH + WT_ROWS) {
        int j = i - WTH;
        float v;
        if (j < 128) v = b0[j];
        else {
            int s = (j - 128) >> 9, t = (j - 128) & 511;
            const float* B = (s == 0) ? b1 : (s == 1) ? b2 : (s == 2) ? b3
                           : (s == 3) ? b4 : (s == 4) ? b5 : b6;
            v = B[t];
        }
        g_biasc[j] = v;
    }
}

// ---------------- activation fp32 -> bf16 hi/lo (x only) ----------------
__global__ void conv_a_k(const float* __restrict__ src, int n4) {
    int i = blockIdx.x * blockDim.x + threadIdx.x;
    if (i < n4) {
        float4 v = ((const float4*)src)[i];
        __nv_bfloat16 hx = __float2bfloat16(v.x);
        __nv_bfloat16 hy = __float2bfloat16(v.y);
        __nv_bfloat16 hz = __float2bfloat16(v.z);
        __nv_bfloat16 hw = __float2bfloat16(v.w);
        __nv_bfloat16 lx = __float2bfloat16(v.x - __bfloat162float(hx));
        __nv_bfloat16 ly = __float2bfloat16(v.y - __bfloat162float(hy));
        __nv_bfloat16 lz = __float2bfloat16(v.z - __bfloat162float(hz));
        __nv_bfloat16 lw = __float2bfloat16(v.w - __bfloat162float(hw));
        ((uint2*)g_ahi)[i] = make_uint2(pack_bf2(hx, hy), pack_bf2(hz, hw));
        ((uint2*)g_alo)[i] = make_uint2(pack_bf2(lx, ly), pack_bf2(lz, lw));
    }
}

// ======== bf16x3 GEMM v4: persistent col tile, double-buffered A, 512 threads ========
#define TSTRIDE 272
#define TILE_B (128 * TSTRIDE)
#define GMM_SMEM (6 * TILE_B)

__device__ __forceinline__ uint32_t smem_u32(const void* p) {
    uint32_t a;
    asm("{ .reg .u64 t; cvta.to.shared.u64 t, %1; cvt.u32.u64 %0, t; }" : "=r"(a) : "l"(p));
    return a;
}

#define CP16(dst, src, sz) \
    asm volatile("cp.async.cg.shared.global [%0], [%1], 16, %2;" \
                 :: "r"(dst), "l"(src), "r"(sz) : "memory")
#define CP_COMMIT() asm volatile("cp.async.commit_group;" ::: "memory")
#define CP_WAIT0()  asm volatile("cp.async.wait_group 0;" ::: "memory")
#define CP_WAIT1()  asm volatile("cp.async.wait_group 1;" ::: "memory")

#define LDMX4(r0, r1, r2, r3, addr) \
    asm volatile("ldmatrix.sync.aligned.m8n8.x4.shared.b16 {%0,%1,%2,%3}, [%4];" \
                 : "=r"(r0), "=r"(r1), "=r"(r2), "=r"(r3) : "r"(addr))

#define MMA_BF16(c, a0, a1, a2, a3, b0, b1) \
    asm volatile("mma.sync.aligned.m16n8k16.row.col.f32.bf16.bf16.f32 " \
                 "{%0,%1,%2,%3}, {%4,%5,%6,%7}, {%8,%9}, {%0,%1,%2,%3};" \
                 : "+f"((c)[0]), "+f"((c)[1]), "+f"((c)[2]), "+f"((c)[3]) \
                 : "r"(a0), "r"(a1), "r"(a2), "r"(a3), "r"(b0), "r"(b1))

__device__ __forceinline__ void prefetch_A(uint32_t uAhi, uint32_t uAlo,
                                           const __nv_bfloat16* Ahi, const __nv_bfloat16* Alo,
                                           int row0, int M, int tid) {
    #pragma unroll
    for (int it = 0; it < 4; ++it) {
        int idx = it * 512 + tid;
        int row = idx >> 4, c = idx & 15;
        int grow = row0 + row;
        int ok = grow < M;
        int srow = ok ? grow : 0;
        uint32_t sz = ok ? 16u : 0u;
        CP16(uAhi + row * TSTRIDE + c * 16,
             (const char*)(Ahi + (size_t)srow * 128) + c * 16, sz);
        CP16(uAlo + row * TSTRIDE + c * 16,
             (const char*)(Alo + (size_t)srow * 128) + c * 16, sz);
    }
}

__global__ void __launch_bounds__(512, 1)
gemm_mma_k(const __nv_bfloat16* __restrict__ Ahi, const __nv_bfloat16* __restrict__ Alo, int M,
           const __nv_bfloat16* __restrict__ Bhi, const __nv_bfloat16* __restrict__ Blo,
           const float* __restrict__ bias,
           float* __restrict__ out, float* __restrict__ out2, int split,
           int ldo, int do_relu, int conv_out) {
    extern __shared__ char sm[];
    char* sBhi = sm;
    char* sBlo = sm + TILE_B;
    char* sA[2][2];
    sA[0][0] = sm + 2 * TILE_B;
    sA[0][1] = sm + 3 * TILE_B;
    sA[1][0] = sm + 4 * TILE_B;
    sA[1][1] = sm + 5 * TILE_B;

    int tid = threadIdx.x;
    int wc0 = blockIdx.y * 128;
    int oc  = wc0;
    if (oc >= split) { out = out2; oc -= split; }

    uint32_t uBhi = smem_u32(sBhi), uBlo = smem_u32(sBlo);
    uint32_t uA[2][2];
    #pragma unroll
    for (int s = 0; s < 2; ++s) { uA[s][0] = smem_u32(sA[s][0]); uA[s][1] = smem_u32(sA[s][1]); }

    #pragma unroll
    for (int it = 0; it < 4; ++it) {
        int idx = it * 512 + tid;
        int row = idx >> 4, c = idx & 15;
        CP16(uBhi + row * TSTRIDE + c * 16,
             (const char*)(Bhi + (size_t)(wc0 + row) * 128) + c * 16, 16u);
        CP16(uBlo + row * TSTRIDE + c * 16,
             (const char*)(Blo + (size_t)(wc0 + row) * 128) + c * 16, 16u);
    }
    int nrt = (M + 127) >> 7;
    int stride = gridDim.x;
    int r0 = blockIdx.x;
    if (r0 < nrt)
        prefetch_A(uA[0][0], uA[0][1], Ahi, Alo, r0 * 128, M, tid);
    CP_COMMIT();

    int wid = tid >> 5;
    int lane = tid & 31;
    int m0 = (wid & 3) * 32;
    int n0 = (wid >> 2) * 32;

    int gq = lane >> 3, l8 = lane & 7;
    int fr_row = (gq & 1) * 8 + l8;
    int fr_col = (gq >> 1) * 16;

    uint32_t aoff[2], boff[2];
    #pragma unroll
    for (int mt = 0; mt < 2; ++mt)
        aoff[mt] = (uint32_t)((m0 + mt * 16 + fr_row) * TSTRIDE + fr_col);
    #pragma unroll
    for (int nt2 = 0; nt2 < 2; ++nt2)
        boff[nt2] = (uint32_t)((n0 + nt2 * 16 + fr_row) * TSTRIDE + fr_col);

    int qr = lane >> 2;
    int qc = (lane & 3) * 2;
    float2 bv[4];
    #pragma unroll
    for (int nt = 0; nt < 4; ++nt)
        bv[nt] = *(const float2*)(bias + wc0 + n0 + nt * 8 + qc);

    int buf = 0;
    for (int r = r0; r < nrt; r += stride) {
        int rn = r + stride;
        if (rn < nrt)
            prefetch_A(uA[buf ^ 1][0], uA[buf ^ 1][1], Ahi, Alo, rn * 128, M, tid);
        CP_COMMIT();
        if (rn < nrt) CP_WAIT1(); else CP_WAIT0();
        __syncthreads();

        uint32_t uAhi = uA[buf][0], uAlo = uA[buf][1];

        float c[2][4][4];
        #pragma unroll
        for (int mt = 0; mt < 2; ++mt)
            #pragma unroll
            for (int nt = 0; nt < 4; ++nt)
                #pragma unroll
                for (int q = 0; q < 4; ++q) c[mt][nt][q] = 0.f;

        #pragma unroll
        for (int kk = 0; kk < 8; ++kk) {
            uint32_t ah[2][4], al2[2][4];
            #pragma unroll
            for (int mt = 0; mt < 2; ++mt) {
                LDMX4(ah[mt][0], ah[mt][1], ah[mt][2], ah[mt][3], uAhi + aoff[mt] + kk * 32);
                LDMX4(al2[mt][0], al2[mt][1], al2[mt][2], al2[mt][3], uAlo + aoff[mt] + kk * 32);
            }
            uint32_t bh[2][4], bl[2][4];
            #pragma unroll
            for (int nt2 = 0; nt2 < 2; ++nt2) {
                LDMX4(bh[nt2][0], bh[nt2][1], bh[nt2][2], bh[nt2][3], uBhi + boff[nt2] + kk * 32);
                LDMX4(bl[nt2][0], bl[nt2][1], bl[nt2][2], bl[nt2][3], uBlo + boff[nt2] + kk * 32);
            }
            #pragma unroll
            for (int mt = 0; mt < 2; ++mt)
                #pragma unroll
                for (int nt = 0; nt < 4; ++nt) {
                    int nt2 = nt >> 1, odd = nt & 1;
                    MMA_BF16(c[mt][nt], ah[mt][0], ah[mt][1], ah[mt][2], ah[mt][3],
                             bh[nt2][odd], bh[nt2][2 + odd]);
                    MMA_BF16(c[mt][nt], ah[mt][0], ah[mt][1], ah[mt][2], ah[mt][3],
                             bl[nt2][odd], bl[nt2][2 + odd]);
                    MMA_BF16(c[mt][nt], al2[mt][0], al2[mt][1], al2[mt][2], al2[mt][3],
                             bh[nt2][odd], bh[nt2][2 + odd]);
                }
        }

        int row0 = r * 128;
        #pragma unroll
        for (int mt = 0; mt < 2; ++mt) {
            int r_lo = row0 + m0 + mt * 16 + qr;
            #pragma unroll
            for (int nt = 0; nt < 4; ++nt) {
                int colb = n0 + nt * 8 + qc;
                float2 v0 = make_float2(c[mt][nt][0] + bv[nt].x, c[mt][nt][1] + bv[nt].y);
                float2 v1 = make_float2(c[mt][nt][2] + bv[nt].x, c[mt][nt][3] + bv[nt].y);
                if (do_relu) {
                    v0.x = fmaxf(v0.x, 0.f); v0.y = fmaxf(v0.y, 0.f);
                    v1.x = fmaxf(v1.x, 0.f); v1.y = fmaxf(v1.y, 0.f);
                }
                #pragma unroll
                for (int half = 0; half < 2; ++half) {
                    int rr = r_lo + half * 8;
                    float2 vv = half ? v1 : v0;
                    if (rr < M) {
                        *(float2*)(out + (size_t)rr * ldo + oc + colb) = vv;
                        if (conv_out) {
                            __nv_bfloat16 hx = __float2bfloat16(vv.x);
                            __nv_bfloat16 hy = __float2bfloat16(vv.y);
                            __nv_bfloat16 lx = __float2bfloat16(vv.x - __bfloat162float(hx));
                            __nv_bfloat16 ly = __float2bfloat16(vv.y - __bfloat162float(hy));
                            size_t ai = (size_t)rr * 128 + oc + colb;
                            *(uint32_t*)(g_ahi + ai) = pack_bf2(hx, hy);
                            *(uint32_t*)(g_alo + ai) = pack_bf2(lx, ly);
                        }
                    }
                }
            }
        }
        __syncthreads();
        buf ^= 1;
    }
}

// ===== GATv2 (R6/R8 math), 64-thread blocks for fine-grained load balance =====
#define LRD(t, x4, r4, a4) do {                                        \
    float ex = (x4).x + (r4).x; ex = fmaxf(ex, 0.2f * ex); t = fmaf(ex, (a4).x, t); \
    float ey = (x4).y + (r4).y; ey = fmaxf(ey, 0.2f * ey); t = fmaf(ey, (a4).y, t); \
    float ez = (x4).z + (r4).z; ez = fmaxf(ez, 0.2f * ez); t = fmaf(ez, (a4).z, t); \
    float ew = (x4).w + (r4).w; ew = fmaxf(ew, 0.2f * ew); t = fmaf(ew, (a4).w, t); \
} while (0)

template <int WRITE_H>
__global__ void __launch_bounds__(64)
gat2_k(const float* __restrict__ xlxr,
       const float* __restrict__ hres,
       const float* __restrict__ att,
       const float* __restrict__ gatb,
       const float* __restrict__ lng,
       const float* __restrict__ lnb,
       const float* __restrict__ headW,
       const float* __restrict__ headb,
       float* __restrict__ outh,
       float* __restrict__ outsc,
       int N) {
    int n    = (blockIdx.x * blockDim.x + threadIdx.x) >> 5;
    int lane = threadIdx.x & 31;
    if (n >= N) return;
    int g  = lane >> 3;
    int l8 = lane & 7;
    int cb = g * 32 + l8 * 4;

    float4 atv[4], xrv[4];
    const float4* ap = (const float4*)att + cb;
    const float4* xp = (const float4*)(xlxr + (size_t)n * 1024 + 512) + cb;
    #pragma unroll
    for (int j = 0; j < 4; ++j) { atv[j] = ap[j]; xrv[j] = xp[j]; }

    float m = -CUDART_INF_F, d = 0.f;
    float4 acc[4];
    #pragma unroll
    for (int j = 0; j < 4; ++j) acc[j] = make_float4(0.f, 0.f, 0.f, 0.f);

    int e = g_rp[n], end = g_rp[n + 1];
    for (; e + 2 <= end; e += 2) {
        int s0 = g_csrc[e];
        int s1 = g_csrc[e + 1];
        const float4* q0 = (const float4*)(xlxr + (size_t)s0 * 1024) + cb;
        const float4* q1 = (const float4*)(xlxr + (size_t)s1 * 1024) + cb;
        float4 x0[4], x1[4];
        #pragma unroll
        for (int j = 0; j < 4; ++j) x0[j] = q0[j];
        #pragma unroll
        for (int j = 0; j < 4; ++j) x1[j] = q1[j];

        float t0 = 0.f, t1 = 0.f;
        #pragma unroll
        for (int j = 0; j < 4; ++j) { LRD(t0, x0[j], xrv[j], atv[j]); LRD(t1, x1[j], xrv[j], atv[j]); }
        t0 += __shfl_xor_sync(0xffffffffu, t0, 1);
        t1 += __shfl_xor_sync(0xffffffffu, t1, 1);
        t0 += __shfl_xor_sync(0xffffffffu, t0, 2);
        t1 += __shfl_xor_sync(0xffffffffu, t1, 2);
        t0 += __shfl_xor_sync(0xffffffffu, t0, 4);
        t1 += __shfl_xor_sync(0xffffffffu, t1, 4);

        float mn = fmaxf(m, fmaxf(t0, t1));
        float sc = __expf(m - mn);
        float p0 = __expf(t0 - mn);
        float p1 = __expf(t1 - mn);
        d = fmaf(d, sc, p0 + p1);
        #pragma unroll
        for (int j = 0; j < 4; ++j) {
            acc[j].x = fmaf(acc[j].x, sc, fmaf(p0, x0[j].x, p1 * x1[j].x));
            acc[j].y = fmaf(acc[j].y, sc, fmaf(p0, x0[j].y, p1 * x1[j].y));
            acc[j].z = fmaf(acc[j].z, sc, fmaf(p0, x0[j].z, p1 * x1[j].z));
            acc[j].w = fmaf(acc[j].w, sc, fmaf(p0, x0[j].w, p1 * x1[j].w));
        }
        m = mn;
    }
    if (e < end) {
        int s0 = g_csrc[e];
        const float4* q0 = (const float4*)(xlxr + (size_t)s0 * 1024) + cb;
        float4 x0[4];
        #pragma unroll
        for (int j = 0; j < 4; ++j) x0[j] = q0[j];
        float t0 = 0.f;
        #pragma unroll
        for (int j = 0; j < 4; ++j) LRD(t0, x0[j], xrv[j], atv[j]);
        t0 += __shfl_xor_sync(0xffffffffu, t0, 1);
        t0 += __shfl_xor_sync(0xffffffffu, t0, 2);
        t0 += __shfl_xor_sync(0xffffffffu, t0, 4);
        float mn = fmaxf(m, t0);
        float sc = __expf(m - mn);
        float p0 = __expf(t0 - mn);
        d = fmaf(d, sc, p0);
        #pragma unroll
        for (int j = 0; j < 4; ++j) {
            acc[j].x = fmaf(acc[j].x, sc, p0 * x0[j].x);
            acc[j].y = fmaf(acc[j].y, sc, p0 * x0[j].y);
            acc[j].z = fmaf(acc[j].z, sc, p0 * x0[j].z);
            acc[j].w = fmaf(acc[j].w, sc, p0 * x0[j].w);
        }
        m = mn;
    }

    float inv = 0.25f / d;
    float* a = (float*)acc;
    #pragma unroll
    for (int i = 0; i < 16; ++i) {
        float v = a[i] * inv;
        v += __shfl_xor_sync(0xffffffffu, v, 8);
        v += __shfl_xor_sync(0xffffffffu, v, 16);
        a[i] = v;
    }

    int fb = l8 * 4;
    const float4* gbp = (const float4*)gatb + fb;
    const float4* hrp = (const float4*)(hres + (size_t)n * 128) + fb;
    float4 v4[4];
    float s1 = 0.f, s2 = 0.f;
    #pragma unroll
    for (int j = 0; j < 4; ++j) {
        float4 gb = gbp[j], hr = hrp[j];
        v4[j].x = acc[j].x + gb.x + hr.x;
        v4[j].y = acc[j].y + gb.y + hr.y;
        v4[j].z = acc[j].z + gb.z + hr.z;
        v4[j].w = acc[j].w + gb.w + hr.w;
        s1 += v4[j].x + v4[j].y + v4[j].z + v4[j].w;
        s2 += v4[j].x * v4[j].x + v4[j].y * v4[j].y + v4[j].z * v4[j].z + v4[j].w * v4[j].w;
    }
    s1 += __shfl_xor_sync(0xffffffffu, s1, 1);
    s2 += __shfl_xor_sync(0xffffffffu, s2, 1);
    s1 += __shfl_xor_sync(0xffffffffu, s1, 2);
    s2 += __shfl_xor_sync(0xffffffffu, s2, 2);
    s1 += __shfl_xor_sync(0xffffffffu, s1, 4);
    s2 += __shfl_xor_sync(0xffffffffu, s2, 4);
    float mean = s1 * (1.f / 128.f);
    float var  = s2 * (1.f / 128.f) - mean * mean;
    float rstd = rsqrtf(var + 1e-5f);

    const float4* gp = (const float4*)lng + fb;
    const float4* bp = (const float4*)lnb + fb;
    float4 y4[4];
    #pragma unroll
    for (int j = 0; j < 4; ++j) {
        float4 gg = gp[j], bb = bp[j];
        y4[j].x = fmaxf((v4[j].x - mean) * rstd * gg.x + bb.x, 0.f);
        y4[j].y = fmaxf((v4[j].y - mean) * rstd * gg.y + bb.y, 0.f);
        y4[j].z = fmaxf((v4[j].z - mean) * rstd * gg.z + bb.z, 0.f);
        y4[j].w = fmaxf((v4[j].w - mean) * rstd * gg.w + bb.w, 0.f);
    }

    if (WRITE_H) {
        if (g == 0) {
            float4* op = (float4*)outh + (size_t)n * 32 + fb;
            #pragma unroll
            for (int j = 0; j < 4; ++j) {
                op[j] = y4[j];
                __nv_bfloat16 hx = __float2bfloat16(y4[j].x);
                __nv_bfloat16 hy = __float2bfloat16(y4[j].y);
                __nv_bfloat16 hz = __float2bfloat16(y4[j].z);
                __nv_bfloat16 hw = __float2bfloat16(y4[j].w);
                __nv_bfloat16 lx = __float2bfloat16(y4[j].x - __bfloat162float(hx));
                __nv_bfloat16 ly = __float2bfloat16(y4[j].y - __bfloat162float(hy));
                __nv_bfloat16 lz = __float2bfloat16(y4[j].z - __bfloat162float(hz));
                __nv_bfloat16 lw = __float2bfloat16(y4[j].w - __bfloat162float(hw));
                size_t ai = (size_t)n * 32 + fb + j;
                ((uint2*)g_ahi)[ai] = make_uint2(pack_bf2(hx, hy), pack_bf2(hz, hw));
                ((uint2*)g_alo)[ai] = make_uint2(pack_bf2(lx, ly), pack_bf2(lz, lw));
            }
        }
    } else {
        const float4* wp = (const float4*)headW + fb;
        float pp = 0.f;
        #pragma unroll
        for (int j = 0; j < 4; ++j) {
            float4 w4 = wp[j];
            pp = fmaf(y4[j].x, w4.x, pp);
            pp = fmaf(y4[j].y, w4.y, pp);
            pp = fmaf(y4[j].z, w4.z, pp);
            pp = fmaf(y4[j].w, w4.w, pp);
        }
        pp += __shfl_xor_sync(0xffffffffu, pp, 1);
        pp += __shfl_xor_sync(0xffffffffu, pp, 2);
        pp += __shfl_xor_sync(0xffffffffu, pp, 4);
        if (lane == 0) outsc[n] = pp + headb[0];
    }
}

// ---------------- launch ----------------
extern "C" void kernel_launch(void* const* d_in, const int* in_sizes, int n_in,
                              void* d_out, int out_size) {
    const float* x     = (const float*)d_in[0];
    const int*   ei    = (const int*)d_in[1];
    const float* W_in  = (const float*)d_in[2];
    const float* b_in  = (const float*)d_in[3];
    const float* c1_Wl = (const float*)d_in[4];
    const float* c1_bl = (const float*)d_in[5];
    const float* c1_Wr = (const float*)d_in[6];
    const float* c1_br = (const float*)d_in[7];
    const float* c1_att= (const float*)d_in[8];
    const float* c1_b  = (const float*)d_in[9];
    const float* ln1_g = (const float*)d_in[10];
    const float* ln1_b = (const float*)d_in[11];
    const float* a_Wl  = (const float*)d_in[12];
    const float* a_bl  = (const float*)d_in[13];
    const float* a_Wr  = (const float*)d_in[14];
    const float* a_br  = (const float*)d_in[15];
    const float* a_att = (const float*)d_in[16];
    const float* a_b   = (const float*)d_in[17];
    const float* aln_g = (const float*)d_in[18];
    const float* aln_b = (const float*)d_in[19];
    const float* ah_W  = (const float*)d_in[20];
    const float* ah_b  = (const float*)d_in[21];
    const float* k_Wl  = (const float*)d_in[22];
    const float* k_bl  = (const float*)d_in[23];
    const float* k_Wr  = (const float*)d_in[24];
    const float* k_br  = (const float*)d_in[25];
    const float* k_att = (const float*)d_in[26];
    const float* k_b   = (const float*)d_in[27];
    const float* kln_g = (const float*)d_in[28];
    const float* kln_b = (const float*)d_in[29];
    const float* kh_W  = (const float*)d_in[30];
    const float* kh_b  = (const float*)d_in[31];

    int N = in_sizes[0] / 128;
    int E = in_sizes[1] / 2;
    float* out = (float*)d_out;

    float *h1, *h2, *xlxr, *xlxr2, *biasc;
    __nv_bfloat16 *ahi, *alo, *wthi, *wtlo;
    cudaGetSymbolAddress((void**)&h1, g_h1);
    cudaGetSymbolAddress((void**)&h2, g_h2);
    cudaGetSymbolAddress((void**)&xlxr, g_xlxr);
    cudaGetSymbolAddress((void**)&xlxr2, g_xlxr2);
    cudaGetSymbolAddress((void**)&biasc, g_biasc);
    cudaGetSymbolAddress((void**)&ahi, g_ahi);
    cudaGetSymbolAddress((void**)&alo, g_alo);
    cudaGetSymbolAddress((void**)&wthi, g_wthi);
    cudaGetSymbolAddress((void**)&wtlo, g_wtlo);

    cudaFuncSetAttribute(gemm_mma_k, cudaFuncAttributeMaxDynamicSharedMemorySize, GMM_SMEM);

    int gg64 = (N * 2 + 1) / 2;            // blocks of 64 threads = 2 warps -> ceil(N/2)
    gg64 = (N + 1) / 2;
    int gc = (N * 32 + 255) / 256;
    const int NOSPLIT = 1 << 30;

    conv_all_k<<<(2048 + 6 * 8192 + WT_ROWS + 255) / 256, 256>>>(          // 1
        W_in, c1_Wl, c1_Wr, a_Wl, a_Wr, k_Wl, k_Wr,
        b_in, c1_bl, c1_br, a_bl, a_br, k_bl, k_br, N);
    conv_a_k<<<gc, 256>>>(x, N * 32);                                      // 2
    gemm_mma_k<<<dim3(148, 1), 512, GMM_SMEM>>>(ahi, alo, N,               // 3: input layer
        wthi, wtlo, biasc, h1, (float*)0, NOSPLIT, 128, 1, 1);
    gemm_mma_k<<<dim3(18, 8), 512, GMM_SMEM>>>(ahi, alo, N,                // 4 <- profiled
        wthi + (size_t)128 * 128, wtlo + (size_t)128 * 128, biasc + 128,
        xlxr, (float*)0, NOSPLIT, 1024, 0, 0);

    count_k<<<(E + 255) / 256, 256>>>(ei + E, E);                          // 5
    scan2_k<<<1, 1024>>>(N);                                               // 6
    scatter_k<<<(E + N + 255) / 256, 256>>>(ei, ei + E, E, N);             // 7

    gat2_k<1><<<gg64, 64>>>(xlxr, h1, c1_att, c1_b, ln1_g, ln1_b,          // 8
                            (const float*)0, (const float*)0, h2, (float*)0, N);

    gemm_mma_k<<<dim3(9, 16), 512, GMM_SMEM>>>(ahi, alo, N,                // 9
        wthi + (size_t)1152 * 128, wtlo + (size_t)1152 * 128, biasc + 1152,
        xlxr, xlxr2, 1024, 1024, 0, 0);

    gat2_k<0><<<gg64, 64>>>(xlxr, h2, a_att, a_b, aln_g, aln_b,            // 10
                            ah_W, ah_b, (float*)0, out, N);
    gat2_k<0><<<gg64, 64>>>(xlxr2, h2, k_att, k_b, kln_g, kln_b,           // 11
                            kh_W, kh_b, (float*)0, out + N, N);
}